// round 8
// baseline (speedup 1.0000x reference)
#include <cuda_runtime.h>
#include <cuda_fp16.h>
#include <math.h>

#define NN 100000
#define NE 1600000
#define EP (NE + NN)          // edges + self loops
#define HID 64
#define LAYERS 3

#define SCAN_T 512
#define NB1 ((NN + SCAN_T - 1) / SCAN_T)   // 196
#define DBINS 1024                          // degree buckets (clamped)

// ---------------- scratch (device globals; no allocation allowed) ----------
__device__ float   g_x[NN * HID];    // current features / residual
__device__ __half2 g_xlh[NN * 32];   // xl in fp16 (64 halves = 128B per node)
__device__ float   g_xr[NN * HID];
__device__ int     g_deg[NN];        // histogram, then scatter cursor
__device__ int     g_off[NN + 1];    // CSR offsets (exclusive scan)
__device__ int     g_srcs[EP];       // CSR: src node per incoming edge
__device__ int     g_bsum[NB1];      // scan block sums
__device__ int     g_dcnt[DBINS + 1];// degree-bucket counts, then cursors
__device__ int     g_order[NN];      // nodes sorted by descending degree

// ---------------- 1) input projection + zero histograms --------------------
__global__ void k_proj(const float* __restrict__ coords,
                       const float* __restrict__ Wp,
                       const float* __restrict__ bp) {
    int i = blockIdx.x * blockDim.x + threadIdx.x;
    if (i >= NN * HID) return;
    int n = i >> 6, c = i & 63;
    float c0 = coords[n * 2 + 0];
    float c1 = coords[n * 2 + 1];
    g_x[i] = fmaf(c0, Wp[c], fmaf(c1, Wp[64 + c], bp[c]));
    if (i < NN) g_deg[i] = 0;
    if (i < DBINS + 1) g_dcnt[i] = 0;
}

// ---------------- 2) CSR build: histogram over destinations ----------------
__global__ void k_hist(const int* __restrict__ ei) {
    int e = blockIdx.x * blockDim.x + threadIdx.x;
    if (e >= EP) return;
    int d = (e < NE) ? ei[NE + e] : (e - NE);
    atomicAdd(&g_deg[d], 1);
}

// ---------------- 3) scan level 1 (warp-shuffle based) ---------------------
__global__ void k_scan1() {
    __shared__ int wsum[SCAN_T / 32];          // 16 warp totals
    int t = threadIdx.x, b = blockIdx.x, i = b * SCAN_T + t;
    int lane = t & 31, wid = t >> 5;
    int v = (i < NN) ? g_deg[i] : 0;
    int x = v;
#pragma unroll
    for (int o = 1; o < 32; o <<= 1) {
        int u = __shfl_up_sync(0xffffffffu, x, o);
        if (lane >= o) x += u;
    }
    if (lane == 31) wsum[wid] = x;
    __syncthreads();
    if (wid == 0) {
        int ws = (lane < SCAN_T / 32) ? wsum[lane] : 0;
        int y = ws;
#pragma unroll
        for (int o = 1; o < 16; o <<= 1) {
            int u = __shfl_up_sync(0xffffffffu, y, o);
            if (lane >= o) y += u;
        }
        if (lane < SCAN_T / 32) wsum[lane] = y - ws;   // exclusive warp offs
        if (lane == SCAN_T / 32 - 1) g_bsum[b] = y;    // block total
    }
    __syncthreads();
    if (i < NN) g_off[i] = x - v + wsum[wid];          // exclusive in block
}

// ---------------- 4) scan level 2 fused: add prefix of block sums ----------
__global__ void k_scan3() {
    __shared__ int sprev;
    int t = threadIdx.x, b = blockIdx.x, i = b * SCAN_T + t;
    if (t < 32) {
        int acc = 0;
        for (int j = t; j < b; j += 32) acc += g_bsum[j];
#pragma unroll
        for (int o = 16; o; o >>= 1) acc += __shfl_xor_sync(0xffffffffu, acc, o);
        if (t == 0) sprev = acc;
    }
    __syncthreads();
    int prev = sprev;
    if (i < NN) {
        int o = g_off[i] + prev;
        g_off[i] = o;
        g_deg[i] = o;                          // reuse as scatter cursor
    }
    if (i == 0) g_off[NN] = EP;
}

// ---------------- 5) CSR scatter --------------------------------------------
__global__ void k_scatter(const int* __restrict__ ei) {
    int e = blockIdx.x * blockDim.x + threadIdx.x;
    if (e >= EP) return;
    int s, d;
    if (e < NE) { s = ei[e]; d = ei[NE + e]; }
    else        { s = e - NE; d = s; }
    int pos = atomicAdd(&g_deg[d], 1);
    g_srcs[pos] = s;
}

// ---------------- 6) degree sort: histogram / bases / scatter ---------------
__global__ void k_sorthist() {
    int i = blockIdx.x * blockDim.x + threadIdx.x;
    if (i >= NN) return;
    int deg = g_off[i + 1] - g_off[i];
    atomicAdd(&g_dcnt[min(deg, DBINS)], 1);
}

__global__ void k_sortscan() {          // descending-degree bucket bases
    if (threadIdx.x == 0) {
        int acc = 0;
        for (int b = DBINS; b >= 0; b--) {
            int c = g_dcnt[b];
            g_dcnt[b] = acc;            // base for bucket b
            acc += c;
        }
    }
}

__global__ void k_sortscatter() {
    int i = blockIdx.x * blockDim.x + threadIdx.x;
    if (i >= NN) return;
    int deg = g_off[i + 1] - g_off[i];
    int pos = atomicAdd(&g_dcnt[min(deg, DBINS)], 1);
    g_order[pos] = i;
}

// ---------------- 7) fused GEMM: xl(fp16) = x@Wl+bl ; xr = x@Wr+br ----------
__global__ __launch_bounds__(256, 4)
void k_gemm(const float* __restrict__ Wl, const float* __restrict__ bl,
            const float* __restrict__ Wr, const float* __restrict__ br) {
    __shared__ float Ws[64][128];    // combined [k][c]: c<64 -> Wl, c>=64 -> Wr
    __shared__ float xs[32][64];
    int tid  = threadIdx.x;
    int row0 = blockIdx.x * 32;

    for (int j = tid; j < 64 * 128; j += 256) {
        int k = j >> 7, c = j & 127;
        Ws[k][c] = (c < 64) ? Wl[k * 64 + c] : Wr[k * 64 + (c - 64)];
    }
    for (int j = tid; j < 32 * 16; j += 256) {
        int r = j >> 4, kq = j & 15;
        *(float4*)&xs[r][kq * 4] =
            *(const float4*)&g_x[(row0 + r) * 64 + kq * 4];
    }
    __syncthreads();

    int tx = tid & 31, ty = tid >> 5;
    float4 acc[4];
#pragma unroll
    for (int r = 0; r < 4; r++) acc[r] = make_float4(0.f, 0.f, 0.f, 0.f);

#pragma unroll 16
    for (int k = 0; k < 64; k++) {
        float4 w = *(float4*)&Ws[k][tx * 4];
#pragma unroll
        for (int r = 0; r < 4; r++) {
            float xv = xs[ty * 4 + r][k];
            acc[r].x = fmaf(xv, w.x, acc[r].x);
            acc[r].y = fmaf(xv, w.y, acc[r].y);
            acc[r].z = fmaf(xv, w.z, acc[r].z);
            acc[r].w = fmaf(xv, w.w, acc[r].w);
        }
    }

    int c0 = tx * 4;
    if (c0 < 64) {                               // xl -> fp16
        float4 bias = *(const float4*)&bl[c0];
#pragma unroll
        for (int r = 0; r < 4; r++) {
            float4 v = acc[r];
            v.x += bias.x; v.y += bias.y; v.z += bias.z; v.w += bias.w;
            __half2 h0 = __floats2half2_rn(v.x, v.y);
            __half2 h1 = __floats2half2_rn(v.z, v.w);
            int row = row0 + ty * 4 + r;
            g_xlh[row * 32 + (c0 >> 1)]     = h0;
            g_xlh[row * 32 + (c0 >> 1) + 1] = h1;
        }
    } else {                                     // xr -> fp32
        int c1 = c0 - 64;
        float4 bias = *(const float4*)&br[c1];
#pragma unroll
        for (int r = 0; r < 4; r++) {
            float4 v = acc[r];
            v.x += bias.x; v.y += bias.y; v.z += bias.z; v.w += bias.w;
            *(float4*)&g_xr[(row0 + ty * 4 + r) * 64 + c1] = v;
        }
    }
}

// ---------------- 8) FUSED: per-dst attention + softmax + ELU + LN ---------
// One warp per destination node (degree-sorted order -> balanced blocks).
__device__ __forceinline__ float nan2num(float o) {
    if (!isfinite(o)) o = isnan(o) ? 0.f : (o > 0.f ? 1e6f : -1e6f);
    return o;
}

__device__ __forceinline__ float lrelu(float v) {
    return v > 0.f ? v : 0.2f * v;
}

__device__ __forceinline__ float4 ld_xlh(int s, int l) {
    uint2 u = __ldg((const uint2*)&g_xlh[s * 32 + l * 2]);
    __half2 h0 = *(__half2*)&u.x;
    __half2 h1 = *(__half2*)&u.y;
    float2 f0 = __half22float2(h0);
    float2 f1 = __half22float2(h1);
    return make_float4(f0.x, f0.y, f1.x, f1.y);
}

__global__ __launch_bounds__(256)
void k_aggr_ln(const float* __restrict__ att,
               const float* __restrict__ bias_out,
               const float* __restrict__ gamma, const float* __restrict__ beta,
               float* __restrict__ dout, int to_dout) {
    int wg = (blockIdx.x * blockDim.x + threadIdx.x) >> 5;  // sorted slot
    if (wg >= NN) return;
    int w = g_order[wg];                                    // node id
    int lane = threadIdx.x & 31;
    int half = lane >> 4;
    int l    = lane & 15;

    int beg = g_off[w], end = g_off[w + 1];
    int s_fb = __ldg(&g_srcs[beg]);              // fallback src for tail lanes

    float4 xr   = *(const float4*)&g_xr[w * 64 + l * 4];
    float4 at4  = *(const float4*)&att[l * 4];   // flat [h*32+dim]

    float4 acc = make_float4(0.f, 0.f, 0.f, 0.f);
    float  dsum = 0.f;

    // per-half steps; all 32 lanes run identical trip counts (shfl safety)
    int iters = (end - beg + 1) >> 1;            // deg >= 1 (self loop)
    for (int k = 0; k < iters; k += 2) {
        int i0 = beg + 2 * k + half;
        int i1 = i0 + 2;
        bool v0 = (i0 < end);
        bool v1 = (i1 < end);
        int  s0 = v0 ? __ldg(&g_srcs[i0]) : s_fb;
        int  s1 = v1 ? __ldg(&g_srcs[i1]) : s_fb;
        // both gathers issued before dependent math -> 4 lines in flight/warp
        float4 a0 = ld_xlh(s0, l);
        float4 a1 = ld_xlh(s1, l);

        float p0 = lrelu(a0.x + xr.x) * at4.x + lrelu(a0.y + xr.y) * at4.y
                 + lrelu(a0.z + xr.z) * at4.z + lrelu(a0.w + xr.w) * at4.w;
        float p1 = lrelu(a1.x + xr.x) * at4.x + lrelu(a1.y + xr.y) * at4.y
                 + lrelu(a1.z + xr.z) * at4.z + lrelu(a1.w + xr.w) * at4.w;
        p0 += __shfl_xor_sync(0xffffffffu, p0, 1, 8);
        p1 += __shfl_xor_sync(0xffffffffu, p1, 1, 8);
        p0 += __shfl_xor_sync(0xffffffffu, p0, 2, 8);
        p1 += __shfl_xor_sync(0xffffffffu, p1, 2, 8);
        p0 += __shfl_xor_sync(0xffffffffu, p0, 4, 8);
        p1 += __shfl_xor_sync(0xffffffffu, p1, 4, 8);
        float ex0 = v0 ? __expf(p0) : 0.f;       // scores O(1): no max shift
        float ex1 = v1 ? __expf(p1) : 0.f;
        acc.x = fmaf(ex0, a0.x, fmaf(ex1, a1.x, acc.x));
        acc.y = fmaf(ex0, a0.y, fmaf(ex1, a1.y, acc.y));
        acc.z = fmaf(ex0, a0.z, fmaf(ex1, a1.z, acc.z));
        acc.w = fmaf(ex0, a0.w, fmaf(ex1, a1.w, acc.w));
        dsum += ex0 + ex1;
    }

    // combine halves (xor 16 is symmetric: both halves end with full sums)
    acc.x += __shfl_xor_sync(0xffffffffu, acc.x, 16);
    acc.y += __shfl_xor_sync(0xffffffffu, acc.y, 16);
    acc.z += __shfl_xor_sync(0xffffffffu, acc.z, 16);
    acc.w += __shfl_xor_sync(0xffffffffu, acc.w, 16);
    dsum  += __shfl_xor_sync(0xffffffffu, dsum, 16);

    // normalize + bias_out + ELU + residual
    float inv = 1.f / (dsum + 1e-16f);           // lane's own head denom
    float4 bo = *(const float4*)&bias_out[l * 4];
    float4 rx = *(const float4*)&g_x[w * 64 + l * 4];
    float y0 = acc.x * inv + bo.x;
    float y1 = acc.y * inv + bo.y;
    float y2 = acc.z * inv + bo.z;
    float y3 = acc.w * inv + bo.w;
    y0 = y0 > 0.f ? y0 : expm1f(y0);
    y1 = y1 > 0.f ? y1 : expm1f(y1);
    y2 = y2 > 0.f ? y2 : expm1f(y2);
    y3 = y3 > 0.f ? y3 : expm1f(y3);
    y0 += rx.x; y1 += rx.y; y2 += rx.z; y3 += rx.w;

    // LayerNorm over 64 dims (butterfly over the 16-lane group)
    float sum = y0 + y1 + y2 + y3;
#pragma unroll
    for (int o = 1; o < 16; o <<= 1)
        sum += __shfl_xor_sync(0xffffffffu, sum, o, 16);
    float mu = sum * (1.f / 64.f);
    float d0 = y0 - mu, d1 = y1 - mu, d2 = y2 - mu, d3 = y3 - mu;
    float vs = d0 * d0 + d1 * d1 + d2 * d2 + d3 * d3;
#pragma unroll
    for (int o = 1; o < 16; o <<= 1)
        vs += __shfl_xor_sync(0xffffffffu, vs, o, 16);
    float r = rsqrtf(vs * (1.f / 64.f) + 1e-5f);

    float4 gm = *(const float4*)&gamma[l * 4];
    float4 bt = *(const float4*)&beta[l * 4];
    float4 o4;
    o4.x = nan2num(fmaf(d0 * r, gm.x, bt.x));
    o4.y = nan2num(fmaf(d1 * r, gm.y, bt.y));
    o4.z = nan2num(fmaf(d2 * r, gm.z, bt.z));
    o4.w = nan2num(fmaf(d3 * r, gm.w, bt.w));

    if (half == 0) {
        float* outp = to_dout ? dout : g_x;
        *(float4*)&outp[w * 64 + l * 4] = o4;
    }
}

// ---------------- host driver ----------------------------------------------
extern "C" void kernel_launch(void* const* d_in, const int* in_sizes, int n_in,
                              void* d_out, int out_size) {
    const float* coords   = (const float*)d_in[0];
    const int*   ei       = (const int*)  d_in[1];   // int32 (JAX x64 disabled)
    const float* Wp       = (const float*)d_in[2];
    const float* bp       = (const float*)d_in[3];
    const float* Wl       = (const float*)d_in[4];
    const float* bl       = (const float*)d_in[5];
    const float* Wr       = (const float*)d_in[6];
    const float* br       = (const float*)d_in[7];
    const float* att      = (const float*)d_in[8];
    const float* bias_out = (const float*)d_in[9];
    const float* gamma    = (const float*)d_in[10];
    const float* beta     = (const float*)d_in[11];
    float*       outp     = (float*)d_out;

    const int TB = 256;
    const int grid_nh = (NN * HID + TB - 1) / TB;    // 25000
    const int grid_gm = NN / 32;                     // 3125
    const int grid_ep = (EP + TB - 1) / TB;          // 6641
    const int grid_nn = (NN + TB - 1) / TB;          // 391
    const int grid_ag = (NN * 32 + TB - 1) / TB;     // 12500 (warp/node)

    // projection + CSR build + degree sort — once, reused by all layers.
    // gemm layer 0 placed 4th so ncu (-s 5 -c 1) profiles it this round.
    k_proj<<<grid_nh, TB>>>(coords, Wp, bp);
    k_hist<<<grid_ep, TB>>>(ei);
    k_scan1<<<NB1, SCAN_T>>>();
    k_gemm<<<grid_gm, TB>>>(Wl, bl, Wr, br);         // layer 0 (needs proj only)
    k_scan3<<<NB1, SCAN_T>>>();
    k_scatter<<<grid_ep, TB>>>(ei);
    k_sorthist<<<grid_nn, TB>>>();
    k_sortscan<<<1, 32>>>();
    k_sortscatter<<<grid_nn, TB>>>();

    for (int i = 0; i < LAYERS; i++) {
        if (i > 0)
            k_gemm<<<grid_gm, TB>>>(Wl + i * HID * HID, bl + i * HID,
                                    Wr + i * HID * HID, br + i * HID);
        k_aggr_ln<<<grid_ag, TB>>>(att + i * HID, bias_out + i * HID,
                                   gamma + i * HID, beta + i * HID,
                                   outp, (i == LAYERS - 1) ? 1 : 0);
    }
}

// round 9
// speedup vs baseline: 1.3313x; 1.3313x over previous
#include <cuda_runtime.h>
#include <cuda_fp16.h>
#include <math.h>

#define NN 100000
#define NE 1600000
#define EP (NE + NN)          // edges + self loops
#define HID 64
#define LAYERS 3

#define SCAN_T 512
#define NB1 ((NN + SCAN_T - 1) / SCAN_T)   // 196

// ---------------- scratch (device globals; no allocation allowed) ----------
__device__ float   g_x[NN * HID];    // current features / residual
__device__ __half2 g_xlh[NN * 32];   // xl in fp16 (64 halves = 128B per node)
__device__ float   g_xr[NN * HID];
__device__ int     g_deg[NN];        // histogram, then scatter cursor
__device__ int     g_off[NN + 1];    // CSR offsets (exclusive scan)
__device__ int     g_srcs[EP];       // CSR: src node per incoming edge
__device__ int     g_bsum[NB1];      // scan block sums

// ---------------- 1) input projection + zero the degree histogram ----------
__global__ void k_proj(const float* __restrict__ coords,
                       const float* __restrict__ Wp,
                       const float* __restrict__ bp) {
    int i = blockIdx.x * blockDim.x + threadIdx.x;
    if (i >= NN * HID) return;
    int n = i >> 6, c = i & 63;
    float c0 = coords[n * 2 + 0];
    float c1 = coords[n * 2 + 1];
    g_x[i] = fmaf(c0, Wp[c], fmaf(c1, Wp[64 + c], bp[c]));
    if (i < NN) g_deg[i] = 0;
}

// ---------------- 2) CSR build: histogram over destinations ----------------
__global__ void k_hist(const int* __restrict__ ei) {
    int e = blockIdx.x * blockDim.x + threadIdx.x;
    if (e >= EP) return;
    int d = (e < NE) ? ei[NE + e] : (e - NE);
    atomicAdd(&g_deg[d], 1);
}

// ---------------- 3) scan level 1 (warp-shuffle based) ---------------------
__global__ void k_scan1() {
    __shared__ int wsum[SCAN_T / 32];          // 16 warp totals
    int t = threadIdx.x, b = blockIdx.x, i = b * SCAN_T + t;
    int lane = t & 31, wid = t >> 5;
    int v = (i < NN) ? g_deg[i] : 0;
    int x = v;
#pragma unroll
    for (int o = 1; o < 32; o <<= 1) {
        int u = __shfl_up_sync(0xffffffffu, x, o);
        if (lane >= o) x += u;
    }
    if (lane == 31) wsum[wid] = x;
    __syncthreads();
    if (wid == 0) {
        int ws = (lane < SCAN_T / 32) ? wsum[lane] : 0;
        int y = ws;
#pragma unroll
        for (int o = 1; o < 16; o <<= 1) {
            int u = __shfl_up_sync(0xffffffffu, y, o);
            if (lane >= o) y += u;
        }
        if (lane < SCAN_T / 32) wsum[lane] = y - ws;   // exclusive warp offs
        if (lane == SCAN_T / 32 - 1) g_bsum[b] = y;    // block total
    }
    __syncthreads();
    if (i < NN) g_off[i] = x - v + wsum[wid];          // exclusive in block
}

// ---------------- 4) scan level 2 fused: add prefix of block sums ----------
__global__ void k_scan3() {
    __shared__ int sprev;
    int t = threadIdx.x, b = blockIdx.x, i = b * SCAN_T + t;
    if (t < 32) {
        int acc = 0;
        for (int j = t; j < b; j += 32) acc += g_bsum[j];
#pragma unroll
        for (int o = 16; o; o >>= 1) acc += __shfl_xor_sync(0xffffffffu, acc, o);
        if (t == 0) sprev = acc;
    }
    __syncthreads();
    int prev = sprev;
    if (i < NN) {
        int o = g_off[i] + prev;
        g_off[i] = o;
        g_deg[i] = o;                          // reuse as scatter cursor
    }
    if (i == 0) g_off[NN] = EP;
}

// ---------------- 5) CSR scatter --------------------------------------------
__global__ void k_scatter(const int* __restrict__ ei) {
    int e = blockIdx.x * blockDim.x + threadIdx.x;
    if (e >= EP) return;
    int s, d;
    if (e < NE) { s = ei[e]; d = ei[NE + e]; }
    else        { s = e - NE; d = s; }
    int pos = atomicAdd(&g_deg[d], 1);
    g_srcs[pos] = s;
}

// ---------------- 6) fused GEMM: xl(fp16) = x@Wl+bl ; xr = x@Wr+br ----------
// k vectorized by 4: 8 LDS.128 per 64 FMAs/thread (was 20 LDS-equiv).
__global__ __launch_bounds__(256, 4)
void k_gemm(const float* __restrict__ Wl, const float* __restrict__ bl,
            const float* __restrict__ Wr, const float* __restrict__ br) {
    __shared__ float Ws[64][128];    // combined [k][c]: c<64 -> Wl, c>=64 -> Wr
    __shared__ float xs[32][64];
    int tid  = threadIdx.x;
    int row0 = blockIdx.x * 32;

    for (int j = tid; j < 64 * 128; j += 256) {
        int k = j >> 7, c = j & 127;
        Ws[k][c] = (c < 64) ? Wl[k * 64 + c] : Wr[k * 64 + (c - 64)];
    }
    for (int j = tid; j < 32 * 16; j += 256) {
        int r = j >> 4, kq = j & 15;
        *(float4*)&xs[r][kq * 4] =
            *(const float4*)&g_x[(row0 + r) * 64 + kq * 4];
    }
    __syncthreads();

    int tx = tid & 31, ty = tid >> 5;
    float4 acc[4];
#pragma unroll
    for (int r = 0; r < 4; r++) acc[r] = make_float4(0.f, 0.f, 0.f, 0.f);

#pragma unroll
    for (int k4 = 0; k4 < 64; k4 += 4) {
        // broadcast loads (same address warp-wide): one float4 per row
        float4 xv[4];
#pragma unroll
        for (int r = 0; r < 4; r++)
            xv[r] = *(float4*)&xs[ty * 4 + r][k4];
#pragma unroll
        for (int kk = 0; kk < 4; kk++) {
            float4 w = *(float4*)&Ws[k4 + kk][tx * 4];
#pragma unroll
            for (int r = 0; r < 4; r++) {
                float xvk = (&xv[r].x)[kk];
                acc[r].x = fmaf(xvk, w.x, acc[r].x);
                acc[r].y = fmaf(xvk, w.y, acc[r].y);
                acc[r].z = fmaf(xvk, w.z, acc[r].z);
                acc[r].w = fmaf(xvk, w.w, acc[r].w);
            }
        }
    }

    int c0 = tx * 4;
    if (c0 < 64) {                               // xl -> fp16
        float4 bias = *(const float4*)&bl[c0];
#pragma unroll
        for (int r = 0; r < 4; r++) {
            float4 v = acc[r];
            v.x += bias.x; v.y += bias.y; v.z += bias.z; v.w += bias.w;
            __half2 h0 = __floats2half2_rn(v.x, v.y);
            __half2 h1 = __floats2half2_rn(v.z, v.w);
            int row = row0 + ty * 4 + r;
            g_xlh[row * 32 + (c0 >> 1)]     = h0;
            g_xlh[row * 32 + (c0 >> 1) + 1] = h1;
        }
    } else {                                     // xr -> fp32
        int c1 = c0 - 64;
        float4 bias = *(const float4*)&br[c1];
#pragma unroll
        for (int r = 0; r < 4; r++) {
            float4 v = acc[r];
            v.x += bias.x; v.y += bias.y; v.z += bias.z; v.w += bias.w;
            *(float4*)&g_xr[(row0 + ty * 4 + r) * 64 + c1] = v;
        }
    }
}

// ---------------- 7) FUSED: per-dst attention + softmax + ELU + LN ---------
// One warp per destination node (natural order: CSR locality preserved).
__device__ __forceinline__ float nan2num(float o) {
    if (!isfinite(o)) o = isnan(o) ? 0.f : (o > 0.f ? 1e6f : -1e6f);
    return o;
}

__device__ __forceinline__ float lrelu(float v) {
    return v > 0.f ? v : 0.2f * v;
}

__device__ __forceinline__ float4 ld_xlh(int s, int l) {
    uint2 u = __ldg((const uint2*)&g_xlh[s * 32 + l * 2]);
    __half2 h0 = *(__half2*)&u.x;
    __half2 h1 = *(__half2*)&u.y;
    float2 f0 = __half22float2(h0);
    float2 f1 = __half22float2(h1);
    return make_float4(f0.x, f0.y, f1.x, f1.y);
}

__global__ __launch_bounds__(256)
void k_aggr_ln(const float* __restrict__ att,
               const float* __restrict__ bias_out,
               const float* __restrict__ gamma, const float* __restrict__ beta,
               float* __restrict__ dout, int to_dout) {
    int w = (blockIdx.x * blockDim.x + threadIdx.x) >> 5;   // node id
    if (w >= NN) return;
    int lane = threadIdx.x & 31;
    int half = lane >> 4;
    int l    = lane & 15;

    int beg = g_off[w], end = g_off[w + 1];
    int s_fb = __ldg(&g_srcs[beg]);              // fallback src for tail lanes

    float4 xr   = *(const float4*)&g_xr[w * 64 + l * 4];
    float4 at4  = *(const float4*)&att[l * 4];   // flat [h*32+dim]

    float4 acc = make_float4(0.f, 0.f, 0.f, 0.f);
    float  dsum = 0.f;

    // per-half steps; all 32 lanes run identical trip counts (shfl safety)
    int iters = (end - beg + 1) >> 1;            // deg >= 1 (self loop)
    for (int k = 0; k < iters; k += 2) {
        int i0 = beg + 2 * k + half;
        int i1 = i0 + 2;
        bool v0 = (i0 < end);
        bool v1 = (i1 < end);
        int  s0 = v0 ? __ldg(&g_srcs[i0]) : s_fb;
        int  s1 = v1 ? __ldg(&g_srcs[i1]) : s_fb;
        // both gathers issued before dependent math -> 4 lines in flight/warp
        float4 a0 = ld_xlh(s0, l);
        float4 a1 = ld_xlh(s1, l);

        float p0 = lrelu(a0.x + xr.x) * at4.x + lrelu(a0.y + xr.y) * at4.y
                 + lrelu(a0.z + xr.z) * at4.z + lrelu(a0.w + xr.w) * at4.w;
        float p1 = lrelu(a1.x + xr.x) * at4.x + lrelu(a1.y + xr.y) * at4.y
                 + lrelu(a1.z + xr.z) * at4.z + lrelu(a1.w + xr.w) * at4.w;
        p0 += __shfl_xor_sync(0xffffffffu, p0, 1, 8);
        p1 += __shfl_xor_sync(0xffffffffu, p1, 1, 8);
        p0 += __shfl_xor_sync(0xffffffffu, p0, 2, 8);
        p1 += __shfl_xor_sync(0xffffffffu, p1, 2, 8);
        p0 += __shfl_xor_sync(0xffffffffu, p0, 4, 8);
        p1 += __shfl_xor_sync(0xffffffffu, p1, 4, 8);
        float ex0 = v0 ? __expf(p0) : 0.f;       // scores O(1): no max shift
        float ex1 = v1 ? __expf(p1) : 0.f;
        acc.x = fmaf(ex0, a0.x, fmaf(ex1, a1.x, acc.x));
        acc.y = fmaf(ex0, a0.y, fmaf(ex1, a1.y, acc.y));
        acc.z = fmaf(ex0, a0.z, fmaf(ex1, a1.z, acc.z));
        acc.w = fmaf(ex0, a0.w, fmaf(ex1, a1.w, acc.w));
        dsum += ex0 + ex1;
    }

    // combine halves (xor 16 is symmetric: both halves end with full sums)
    acc.x += __shfl_xor_sync(0xffffffffu, acc.x, 16);
    acc.y += __shfl_xor_sync(0xffffffffu, acc.y, 16);
    acc.z += __shfl_xor_sync(0xffffffffu, acc.z, 16);
    acc.w += __shfl_xor_sync(0xffffffffu, acc.w, 16);
    dsum  += __shfl_xor_sync(0xffffffffu, dsum, 16);

    // normalize + bias_out + ELU + residual
    float inv = 1.f / (dsum + 1e-16f);           // lane's own head denom
    float4 bo = *(const float4*)&bias_out[l * 4];
    float4 rx = *(const float4*)&g_x[w * 64 + l * 4];
    float y0 = acc.x * inv + bo.x;
    float y1 = acc.y * inv + bo.y;
    float y2 = acc.z * inv + bo.z;
    float y3 = acc.w * inv + bo.w;
    y0 = y0 > 0.f ? y0 : expm1f(y0);
    y1 = y1 > 0.f ? y1 : expm1f(y1);
    y2 = y2 > 0.f ? y2 : expm1f(y2);
    y3 = y3 > 0.f ? y3 : expm1f(y3);
    y0 += rx.x; y1 += rx.y; y2 += rx.z; y3 += rx.w;

    // LayerNorm over 64 dims (butterfly over the 16-lane group)
    float sum = y0 + y1 + y2 + y3;
#pragma unroll
    for (int o = 1; o < 16; o <<= 1)
        sum += __shfl_xor_sync(0xffffffffu, sum, o, 16);
    float mu = sum * (1.f / 64.f);
    float d0 = y0 - mu, d1 = y1 - mu, d2 = y2 - mu, d3 = y3 - mu;
    float vs = d0 * d0 + d1 * d1 + d2 * d2 + d3 * d3;
#pragma unroll
    for (int o = 1; o < 16; o <<= 1)
        vs += __shfl_xor_sync(0xffffffffu, vs, o, 16);
    float r = rsqrtf(vs * (1.f / 64.f) + 1e-5f);

    float4 gm = *(const float4*)&gamma[l * 4];
    float4 bt = *(const float4*)&beta[l * 4];
    float4 o4;
    o4.x = nan2num(fmaf(d0 * r, gm.x, bt.x));
    o4.y = nan2num(fmaf(d1 * r, gm.y, bt.y));
    o4.z = nan2num(fmaf(d2 * r, gm.z, bt.z));
    o4.w = nan2num(fmaf(d3 * r, gm.w, bt.w));

    if (half == 0) {
        float* outp = to_dout ? dout : g_x;
        *(float4*)&outp[w * 64 + l * 4] = o4;
    }
}

// ---------------- host driver ----------------------------------------------
extern "C" void kernel_launch(void* const* d_in, const int* in_sizes, int n_in,
                              void* d_out, int out_size) {
    const float* coords   = (const float*)d_in[0];
    const int*   ei       = (const int*)  d_in[1];   // int32 (JAX x64 disabled)
    const float* Wp       = (const float*)d_in[2];
    const float* bp       = (const float*)d_in[3];
    const float* Wl       = (const float*)d_in[4];
    const float* bl       = (const float*)d_in[5];
    const float* Wr       = (const float*)d_in[6];
    const float* br       = (const float*)d_in[7];
    const float* att      = (const float*)d_in[8];
    const float* bias_out = (const float*)d_in[9];
    const float* gamma    = (const float*)d_in[10];
    const float* beta     = (const float*)d_in[11];
    float*       outp     = (float*)d_out;

    const int TB = 256;
    const int grid_nh = (NN * HID + TB - 1) / TB;    // 25000
    const int grid_gm = NN / 32;                     // 3125
    const int grid_ep = (EP + TB - 1) / TB;          // 6641
    const int grid_ag = (NN * 32 + TB - 1) / TB;     // 12500 (warp/node)

    // projection + CSR build — once, reused by all layers.
    // gemm layer 0 at profiled position (4th launch) to verify the LDS fix.
    k_proj<<<grid_nh, TB>>>(coords, Wp, bp);
    k_hist<<<grid_ep, TB>>>(ei);
    k_scan1<<<NB1, SCAN_T>>>();
    k_gemm<<<grid_gm, TB>>>(Wl, bl, Wr, br);         // layer 0 (needs proj only)
    k_scan3<<<NB1, SCAN_T>>>();
    k_scatter<<<grid_ep, TB>>>(ei);

    for (int i = 0; i < LAYERS; i++) {
        if (i > 0)
            k_gemm<<<grid_gm, TB>>>(Wl + i * HID * HID, bl + i * HID,
                                    Wr + i * HID * HID, br + i * HID);
        k_aggr_ln<<<grid_ag, TB>>>(att + i * HID, bias_out + i * HID,
                                   gamma + i * HID, beta + i * HID,
                                   outp, (i == LAYERS - 1) ? 1 : 0);
    }
}

// round 10
// speedup vs baseline: 1.6757x; 1.2587x over previous
#include <cuda_runtime.h>
#include <cuda_fp16.h>
#include <math.h>

#define NN 100000
#define NE 1600000
#define EP (NE + NN)          // edges + self loops
#define HID 64
#define LAYERS 3

#define SCAN_T 512
#define NB1 ((NN + SCAN_T - 1) / SCAN_T)   // 196

// ---------------- scratch (device globals; no allocation allowed) ----------
__device__ float   g_x[NN * HID];    // current features / residual
__device__ __half2 g_xlh[NN * 32];   // xl in fp16 (64 halves = 128B per node)
__device__ float   g_xr[NN * HID];
__device__ int     g_deg[NN];        // histogram, then scatter cursor
__device__ int     g_off[NN + 1];    // CSR offsets (exclusive scan)
__device__ int     g_srcs[EP];       // CSR: src node per incoming edge
__device__ int     g_bsum[NB1];      // scan block sums

__device__ __forceinline__ unsigned smem_u32(const void* p) {
    return (unsigned)__cvta_generic_to_shared(p);
}

// ---------------- 1) input projection + zero the degree histogram ----------
__global__ void k_proj(const float* __restrict__ coords,
                       const float* __restrict__ Wp,
                       const float* __restrict__ bp) {
    int i = blockIdx.x * blockDim.x + threadIdx.x;
    if (i >= NN * HID) return;
    int n = i >> 6, c = i & 63;
    float c0 = coords[n * 2 + 0];
    float c1 = coords[n * 2 + 1];
    g_x[i] = fmaf(c0, Wp[c], fmaf(c1, Wp[64 + c], bp[c]));
    if (i < NN) g_deg[i] = 0;
}

// ---------------- 2) CSR build: histogram over destinations ----------------
__global__ void k_hist(const int* __restrict__ ei) {
    int e = blockIdx.x * blockDim.x + threadIdx.x;
    if (e >= EP) return;
    int d = (e < NE) ? ei[NE + e] : (e - NE);
    atomicAdd(&g_deg[d], 1);
}

// ---------------- 3) scan level 1 (warp-shuffle based) ---------------------
__global__ void k_scan1() {
    __shared__ int wsum[SCAN_T / 32];
    int t = threadIdx.x, b = blockIdx.x, i = b * SCAN_T + t;
    int lane = t & 31, wid = t >> 5;
    int v = (i < NN) ? g_deg[i] : 0;
    int x = v;
#pragma unroll
    for (int o = 1; o < 32; o <<= 1) {
        int u = __shfl_up_sync(0xffffffffu, x, o);
        if (lane >= o) x += u;
    }
    if (lane == 31) wsum[wid] = x;
    __syncthreads();
    if (wid == 0) {
        int ws = (lane < SCAN_T / 32) ? wsum[lane] : 0;
        int y = ws;
#pragma unroll
        for (int o = 1; o < 16; o <<= 1) {
            int u = __shfl_up_sync(0xffffffffu, y, o);
            if (lane >= o) y += u;
        }
        if (lane < SCAN_T / 32) wsum[lane] = y - ws;
        if (lane == SCAN_T / 32 - 1) g_bsum[b] = y;
    }
    __syncthreads();
    if (i < NN) g_off[i] = x - v + wsum[wid];
}

// ---------------- 4) scan level 2 fused: add prefix of block sums ----------
__global__ void k_scan3() {
    __shared__ int sprev;
    int t = threadIdx.x, b = blockIdx.x, i = b * SCAN_T + t;
    if (t < 32) {
        int acc = 0;
        for (int j = t; j < b; j += 32) acc += g_bsum[j];
#pragma unroll
        for (int o = 16; o; o >>= 1) acc += __shfl_xor_sync(0xffffffffu, acc, o);
        if (t == 0) sprev = acc;
    }
    __syncthreads();
    int prev = sprev;
    if (i < NN) {
        int o = g_off[i] + prev;
        g_off[i] = o;
        g_deg[i] = o;
    }
    if (i == 0) g_off[NN] = EP;
}

// ---------------- 5) CSR scatter --------------------------------------------
__global__ void k_scatter(const int* __restrict__ ei) {
    int e = blockIdx.x * blockDim.x + threadIdx.x;
    if (e >= EP) return;
    int s, d;
    if (e < NE) { s = ei[e]; d = ei[NE + e]; }
    else        { s = e - NE; d = s; }
    int pos = atomicAdd(&g_deg[d], 1);
    g_srcs[pos] = s;
}

// ---------------- 6) tensor-core GEMM: [xl|xr] = x @ [Wl|Wr] + bias ---------
// mma.m16n8k16 f16 inputs, f32 accumulate. 128 rows/block, 8 warps (16 rows
// each), 16 n-tiles of 8 cols. Strides padded so ldmatrix is conflict-free.
__global__ __launch_bounds__(256)
void k_gemm(const float* __restrict__ Wl, const float* __restrict__ bl,
            const float* __restrict__ Wr, const float* __restrict__ br) {
    __shared__ __align__(16) __half xsh[128][72];   // stride 144B (r*4 banks)
    __shared__ __align__(16) __half wsh[64][136];   // stride 272B (r*4 banks)
    int tid  = threadIdx.x;
    int row0 = blockIdx.x * 128;

    // W -> fp16 smem (64 x 128), combined [k][c]: c<64 Wl, else Wr
    for (int j = tid; j < 64 * 128 / 4; j += 256) {
        int k = j >> 5;              // (j*4)/128
        int c = (j << 2) & 127;
        float4 v = (c < 64) ? *(const float4*)&Wl[k * 64 + c]
                            : *(const float4*)&Wr[k * 64 + (c - 64)];
        __half2* dst = (__half2*)&wsh[k][c];
        dst[0] = __floats2half2_rn(v.x, v.y);
        dst[1] = __floats2half2_rn(v.z, v.w);
    }
    // x -> fp16 smem (128 x 64), row-guarded
    for (int j = tid; j < 128 * 64 / 4; j += 256) {
        int r = j >> 4;              // (j*4)/64
        int c = (j << 2) & 63;
        int row = row0 + r;
        float4 v = (row < NN) ? *(const float4*)&g_x[row * 64 + c]
                              : make_float4(0.f, 0.f, 0.f, 0.f);
        __half2* dst = (__half2*)&xsh[r][c];
        dst[0] = __floats2half2_rn(v.x, v.y);
        dst[1] = __floats2half2_rn(v.z, v.w);
    }
    __syncthreads();

    int wid  = tid >> 5;             // 0..7 -> rows wid*16..wid*16+15
    int lane = tid & 31;
    int g    = lane >> 2;            // mma row group
    int tig  = lane & 3;

    // preload A fragments for the 4 k-steps (16 regs)
    unsigned A[4][4];
    {
        int m = lane >> 3, r = lane & 7;
#pragma unroll
        for (int ks = 0; ks < 4; ks++) {
            unsigned addr = smem_u32(&xsh[wid * 16 + (m & 1) * 8 + r]
                                        [ks * 16 + (m >> 1) * 8]);
            asm volatile("ldmatrix.sync.aligned.m8n8.x4.shared.b16 "
                         "{%0,%1,%2,%3}, [%4];"
                         : "=r"(A[ks][0]), "=r"(A[ks][1]),
                           "=r"(A[ks][2]), "=r"(A[ks][3]) : "r"(addr));
        }
    }

#pragma unroll
    for (int nt = 0; nt < 16; nt++) {
        float c0 = 0.f, c1 = 0.f, c2 = 0.f, c3 = 0.f;
#pragma unroll
        for (int ks = 0; ks < 4; ks++) {
            unsigned B0, B1;
            int m = (lane >> 3) & 1, r = lane & 7;
            unsigned addr = smem_u32(&wsh[ks * 16 + m * 8 + r][nt * 8]);
            asm volatile("ldmatrix.sync.aligned.m8n8.x2.trans.shared.b16 "
                         "{%0,%1}, [%2];"
                         : "=r"(B0), "=r"(B1) : "r"(addr));
            asm volatile("mma.sync.aligned.m16n8k16.row.col.f32.f16.f16.f32 "
                         "{%0,%1,%2,%3}, {%4,%5,%6,%7}, {%8,%9}, {%0,%1,%2,%3};"
                         : "+f"(c0), "+f"(c1), "+f"(c2), "+f"(c3)
                         : "r"(A[ks][0]), "r"(A[ks][1]),
                           "r"(A[ks][2]), "r"(A[ks][3]), "r"(B0), "r"(B1));
        }
        int col   = nt * 8 + tig * 2;
        int row_a = row0 + wid * 16 + g;
        int row_b = row_a + 8;
        if (col < 64) {                          // xl -> fp16
            float bx = bl[col], by = bl[col + 1];
            if (row_a < NN)
                g_xlh[row_a * 32 + (col >> 1)] = __floats2half2_rn(c0 + bx, c1 + by);
            if (row_b < NN)
                g_xlh[row_b * 32 + (col >> 1)] = __floats2half2_rn(c2 + bx, c3 + by);
        } else {                                 // xr -> fp32
            int cc = col - 64;
            float bx = br[cc], by = br[cc + 1];
            if (row_a < NN)
                *(float2*)&g_xr[row_a * 64 + cc] = make_float2(c0 + bx, c1 + by);
            if (row_b < NN)
                *(float2*)&g_xr[row_b * 64 + cc] = make_float2(c2 + bx, c3 + by);
        }
    }
}

// ---------------- 7) FUSED: per-dst attention + softmax + ELU + LN ---------
__device__ __forceinline__ float nan2num(float o) {
    if (!isfinite(o)) o = isnan(o) ? 0.f : (o > 0.f ? 1e6f : -1e6f);
    return o;
}

__device__ __forceinline__ float lrelu(float v) {
    return v > 0.f ? v : 0.2f * v;
}

__device__ __forceinline__ float4 ld_xlh(int s, int l) {
    uint2 u = __ldg((const uint2*)&g_xlh[s * 32 + l * 2]);
    __half2 h0 = *(__half2*)&u.x;
    __half2 h1 = *(__half2*)&u.y;
    float2 f0 = __half22float2(h0);
    float2 f1 = __half22float2(h1);
    return make_float4(f0.x, f0.y, f1.x, f1.y);
}

__global__ __launch_bounds__(256)
void k_aggr_ln(const float* __restrict__ att,
               const float* __restrict__ bias_out,
               const float* __restrict__ gamma, const float* __restrict__ beta,
               float* __restrict__ dout, int to_dout) {
    int w = (blockIdx.x * blockDim.x + threadIdx.x) >> 5;   // node id
    if (w >= NN) return;
    int lane = threadIdx.x & 31;
    int half = lane >> 4;
    int l    = lane & 15;

    int beg = g_off[w], end = g_off[w + 1];
    int s_fb = __ldg(&g_srcs[beg]);

    float4 xr  = *(const float4*)&g_xr[w * 64 + l * 4];
    float4 at4 = *(const float4*)&att[l * 4];

    float4 acc = make_float4(0.f, 0.f, 0.f, 0.f);
    float  dsum = 0.f;

    int iters = (end - beg + 1) >> 1;            // deg >= 1 (self loop)
    for (int k = 0; k < iters; k += 2) {
        int i0 = beg + 2 * k + half;
        int i1 = i0 + 2;
        bool v0 = (i0 < end);
        bool v1 = (i1 < end);
        int  s0 = v0 ? __ldg(&g_srcs[i0]) : s_fb;
        int  s1 = v1 ? __ldg(&g_srcs[i1]) : s_fb;
        float4 a0 = ld_xlh(s0, l);
        float4 a1 = ld_xlh(s1, l);

        float p0 = lrelu(a0.x + xr.x) * at4.x + lrelu(a0.y + xr.y) * at4.y
                 + lrelu(a0.z + xr.z) * at4.z + lrelu(a0.w + xr.w) * at4.w;
        float p1 = lrelu(a1.x + xr.x) * at4.x + lrelu(a1.y + xr.y) * at4.y
                 + lrelu(a1.z + xr.z) * at4.z + lrelu(a1.w + xr.w) * at4.w;
        p0 += __shfl_xor_sync(0xffffffffu, p0, 1, 8);
        p1 += __shfl_xor_sync(0xffffffffu, p1, 1, 8);
        p0 += __shfl_xor_sync(0xffffffffu, p0, 2, 8);
        p1 += __shfl_xor_sync(0xffffffffu, p1, 2, 8);
        p0 += __shfl_xor_sync(0xffffffffu, p0, 4, 8);
        p1 += __shfl_xor_sync(0xffffffffu, p1, 4, 8);
        float ex0 = v0 ? __expf(p0) : 0.f;
        float ex1 = v1 ? __expf(p1) : 0.f;
        acc.x = fmaf(ex0, a0.x, fmaf(ex1, a1.x, acc.x));
        acc.y = fmaf(ex0, a0.y, fmaf(ex1, a1.y, acc.y));
        acc.z = fmaf(ex0, a0.z, fmaf(ex1, a1.z, acc.z));
        acc.w = fmaf(ex0, a0.w, fmaf(ex1, a1.w, acc.w));
        dsum += ex0 + ex1;
    }

    acc.x += __shfl_xor_sync(0xffffffffu, acc.x, 16);
    acc.y += __shfl_xor_sync(0xffffffffu, acc.y, 16);
    acc.z += __shfl_xor_sync(0xffffffffu, acc.z, 16);
    acc.w += __shfl_xor_sync(0xffffffffu, acc.w, 16);
    dsum  += __shfl_xor_sync(0xffffffffu, dsum, 16);

    float inv = 1.f / (dsum + 1e-16f);
    float4 bo = *(const float4*)&bias_out[l * 4];
    float4 rx = *(const float4*)&g_x[w * 64 + l * 4];
    float y0 = acc.x * inv + bo.x;
    float y1 = acc.y * inv + bo.y;
    float y2 = acc.z * inv + bo.z;
    float y3 = acc.w * inv + bo.w;
    y0 = y0 > 0.f ? y0 : expm1f(y0);
    y1 = y1 > 0.f ? y1 : expm1f(y1);
    y2 = y2 > 0.f ? y2 : expm1f(y2);
    y3 = y3 > 0.f ? y3 : expm1f(y3);
    y0 += rx.x; y1 += rx.y; y2 += rx.z; y3 += rx.w;

    float sum = y0 + y1 + y2 + y3;
#pragma unroll
    for (int o = 1; o < 16; o <<= 1)
        sum += __shfl_xor_sync(0xffffffffu, sum, o, 16);
    float mu = sum * (1.f / 64.f);
    float d0 = y0 - mu, d1 = y1 - mu, d2 = y2 - mu, d3 = y3 - mu;
    float vs = d0 * d0 + d1 * d1 + d2 * d2 + d3 * d3;
#pragma unroll
    for (int o = 1; o < 16; o <<= 1)
        vs += __shfl_xor_sync(0xffffffffu, vs, o, 16);
    float r = rsqrtf(vs * (1.f / 64.f) + 1e-5f);

    float4 gm = *(const float4*)&gamma[l * 4];
    float4 bt = *(const float4*)&beta[l * 4];
    float4 o4;
    o4.x = nan2num(fmaf(d0 * r, gm.x, bt.x));
    o4.y = nan2num(fmaf(d1 * r, gm.y, bt.y));
    o4.z = nan2num(fmaf(d2 * r, gm.z, bt.z));
    o4.w = nan2num(fmaf(d3 * r, gm.w, bt.w));

    if (half == 0) {
        float* outp = to_dout ? dout : g_x;
        *(float4*)&outp[w * 64 + l * 4] = o4;
    }
}

// ---------------- host driver ----------------------------------------------
extern "C" void kernel_launch(void* const* d_in, const int* in_sizes, int n_in,
                              void* d_out, int out_size) {
    const float* coords   = (const float*)d_in[0];
    const int*   ei       = (const int*)  d_in[1];   // int32 (JAX x64 disabled)
    const float* Wp       = (const float*)d_in[2];
    const float* bp       = (const float*)d_in[3];
    const float* Wl       = (const float*)d_in[4];
    const float* bl       = (const float*)d_in[5];
    const float* Wr       = (const float*)d_in[6];
    const float* br       = (const float*)d_in[7];
    const float* att      = (const float*)d_in[8];
    const float* bias_out = (const float*)d_in[9];
    const float* gamma    = (const float*)d_in[10];
    const float* beta     = (const float*)d_in[11];
    float*       outp     = (float*)d_out;

    const int TB = 256;
    const int grid_nh = (NN * HID + TB - 1) / TB;    // 25000
    const int grid_gm = (NN + 127) / 128;            // 782
    const int grid_ep = (EP + TB - 1) / TB;          // 6641
    const int grid_ag = (NN * 32 + TB - 1) / TB;     // 12500 (warp/node)

    // projection + CSR build — once, reused by all layers.
    // gemm layer 0 at profiled position (4th launch) to verify the mma path.
    k_proj<<<grid_nh, TB>>>(coords, Wp, bp);
    k_hist<<<grid_ep, TB>>>(ei);
    k_scan1<<<NB1, SCAN_T>>>();
    k_gemm<<<grid_gm, TB>>>(Wl, bl, Wr, br);         // layer 0 (needs proj only)
    k_scan3<<<NB1, SCAN_T>>>();
    k_scatter<<<grid_ep, TB>>>(ei);

    for (int i = 0; i < LAYERS; i++) {
        if (i > 0)
            k_gemm<<<grid_gm, TB>>>(Wl + i * HID * HID, bl + i * HID,
                                    Wr + i * HID * HID, br + i * HID);
        k_aggr_ln<<<grid_ag, TB>>>(att + i * HID, bias_out + i * HID,
                                   gamma + i * HID, beta + i * HID,
                                   outp, (i == LAYERS - 1) ? 1 : 0);
    }
}